// round 5
// baseline (speedup 1.0000x reference)
#include <cuda_runtime.h>
#include <math.h>

// Gaussian-mixture splat renderer, forward-differenced along grid columns,
// PIXEL-PAIR packed f32x2 (FFMA2-only) arithmetic, single-wave shaping.
//
// c = x_idx*H + y_idx ; px = x_idx/(W-1), py = y_idx/(H-1).
// Per Gaussian k (prescaled by SC = sqrt(0.5*log2 e)):
//   t0 = s10*py + (s00*px + C0),  t1 = s11*py + A1,  e_k = exp2(-(t0^2+t1^2))
// Single-step FD:  e_{j+1} = e_j r_j,  r_{j+1} = r_j * rr,  rr = exp2(-2h^2 a)
// Pair-step FD (lanes = pixels j, j+1):
//   E = (e_j, e_{j+1}),  R = (r_j^2 rr, r_{j+1}^2 rr),  E <- E*R,  R <- R*rr^4
// out = saturate( sum_k w_k e_k / max(1e-7, sum_k e_k) )

#define NK 4
#define PIX 48
#define GM_EPS 1e-7f

typedef unsigned long long u64t;

__device__ __forceinline__ float ex2(float x) {
    float y; asm("ex2.approx.ftz.f32 %0, %1;" : "=f"(y) : "f"(x)); return y;
}
__device__ __forceinline__ u64t pk2(float lo, float hi) {
    u64t r; asm("mov.b64 %0, {%1, %2};" : "=l"(r) : "f"(lo), "f"(hi)); return r;
}
__device__ __forceinline__ void upk2(u64t v, float& lo, float& hi) {
    asm("mov.b64 {%0, %1}, %2;" : "=f"(lo), "=f"(hi) : "l"(v));
}
// The ONLY packed math op used: fma.rn.f32x2 -> native FFMA2.
__device__ __forceinline__ u64t fma2(u64t a, u64t b, u64t c) {
    u64t d; asm("fma.rn.f32x2 %0, %1, %2, %3;" : "=l"(d) : "l"(a), "l"(b), "l"(c)); return d;
}

// ---------------------------------------------------------------------------
// Main kernel: each thread renders PIX consecutive pixels of one column,
// two pixels per packed step. Requires H % PIX == 0.
// ---------------------------------------------------------------------------
__global__ void __launch_bounds__(256, 4) gmix_fd2(
    const float* __restrict__ params,
    float* __restrict__ out,
    int H, int HW, float inv_wm1, float inv_hm1)
{
    const int n  = blockIdx.y;
    const int c0 = (blockIdx.x * blockDim.x + threadIdx.x) * PIX;
    if (c0 >= HW) return;

    const float4* p4 = reinterpret_cast<const float4*>(params + n * 28);
    const float4 MUX = __ldg(p4 + 0);
    const float4 MUY = __ldg(p4 + 1);
    const float4 WKV = __ldg(p4 + 2);
    const float4 SG0 = __ldg(p4 + 3);   // {s00, s01(ignored), s10, s11}
    const float4 SG1 = __ldg(p4 + 4);
    const float4 SG2 = __ldg(p4 + 5);
    const float4 SG3 = __ldg(p4 + 6);

    const float mux[NK] = {MUX.x, MUX.y, MUX.z, MUX.w};
    const float muy[NK] = {MUY.x, MUY.y, MUY.z, MUY.w};
    const float wv [NK] = {WKV.x, WKV.y, WKV.z, WKV.w};
    const float SC = 0.84932180f;       // sqrt(0.5 * log2 e)
    const float s00[NK] = {SG0.x * SC, SG1.x * SC, SG2.x * SC, SG3.x * SC};
    const float s10[NK] = {SG0.z * SC, SG1.z * SC, SG2.z * SC, SG3.z * SC};
    const float s11[NK] = {SG0.w * SC, SG1.w * SC, SG2.w * SC, SG3.w * SC};

    const int   x_idx = c0 / H;
    const int   y0    = c0 - x_idx * H;
    const float px    = (float)x_idx * inv_wm1;
    const float py0   = (float)y0 * inv_hm1;
    const float h     = inv_hm1;

    // Seed packed pair-state per Gaussian.
    u64t E[NK], R[NK], RR4[NK], WD[NK];
#pragma unroll
    for (int k = 0; k < NK; k++) {
        const float C0  = -(s00[k] * mux[k] + s10[k] * muy[k]);
        const float A1  = -s11[k] * muy[k];
        const float a   = fmaf(s10[k], s10[k], s11[k] * s11[k]);
        const float w0n = -(h * h) * a;
        const float un  = -2.0f * h * s10[k];
        const float vn  = -2.0f * h * s11[k];

        const float a0 = fmaf(s00[k], px, C0);
        const float t0 = fmaf(s10[k], py0, a0);
        const float t1 = fmaf(s11[k], py0, A1);

        const float e0 = ex2(fmaf(-t0, t0, -t1 * t1));
        const float r0 = ex2(fmaf(un, t0, fmaf(vn, t1, w0n)));
        const float rr = ex2(w0n + w0n);

        const float e1  = e0 * r0;
        const float r1  = r0 * rr;
        const float rr2 = rr * rr;
        const float rr4 = rr2 * rr2;
        const float R0  = r0 * r0 * rr;
        const float R1  = r1 * r1 * rr;

        E[k]   = pk2(e0, e1);
        R[k]   = pk2(R0, R1);
        RR4[k] = pk2(rr4, rr4);
        WD[k]  = pk2(wv[k], wv[k]);
    }
    const u64t Z2 = pk2(0.0f, 0.0f);
    const u64t O2 = pk2(1.0f, 1.0f);

    float4* outv = reinterpret_cast<float4*>(out + (size_t)n * (size_t)HW + c0);
    float4 res;
    float* rp = &res.x;

#pragma unroll
    for (int jj = 0; jj < PIX / 2; jj++) {      // one iter = 2 pixels
        if (jj > 0) {
            E[0] = fma2(E[0], R[0], Z2);  E[1] = fma2(E[1], R[1], Z2);
            E[2] = fma2(E[2], R[2], Z2);  E[3] = fma2(E[3], R[3], Z2);
            R[0] = fma2(R[0], RR4[0], Z2); R[1] = fma2(R[1], RR4[1], Z2);
            R[2] = fma2(R[2], RR4[2], Z2); R[3] = fma2(R[3], RR4[3], Z2);
        }
        const u64t Ga = fma2(E[0], O2, E[1]);
        const u64t Gb = fma2(E[2], O2, E[3]);
        const u64t G  = fma2(Ga, O2, Gb);
        const u64t A  = fma2(WD[0], E[0],
                        fma2(WD[1], E[1],
                        fma2(WD[2], E[2],
                        fma2(WD[3], E[3], Z2))));
        float g0, g1, a0, a1;
        upk2(G, g0, g1);
        upk2(A, a0, a1);
        const int s = (2 * jj) & 3;
        rp[s]     = __saturatef(__fdividef(a0, fmaxf(GM_EPS, g0)));
        rp[s + 1] = __saturatef(__fdividef(a1, fmaxf(GM_EPS, g1)));
        if ((jj & 1) == 1) outv[jj >> 1] = res;
    }
}

// ---------------------------------------------------------------------------
// Fallback: per-pixel direct evaluation (H % PIX != 0).
// ---------------------------------------------------------------------------
__global__ void __launch_bounds__(256) gmix_generic(
    const float* __restrict__ params,
    float* __restrict__ out,
    int H, int HW, float inv_wm1, float inv_hm1)
{
    const int n = blockIdx.y;
    const float* p = params + n * 28;
    float mux[NK], muy[NK], wkk[NK], s00[NK], s10[NK], s11[NK];
#pragma unroll
    for (int k = 0; k < NK; k++) {
        mux[k] = __ldg(p + k);        muy[k] = __ldg(p + 4 + k);
        wkk[k] = __ldg(p + 8 + k);
        s00[k] = __ldg(p + 12 + 4*k + 0);
        s10[k] = __ldg(p + 12 + 4*k + 2);
        s11[k] = __ldg(p + 12 + 4*k + 3);
    }
    const int c = blockIdx.x * blockDim.x + threadIdx.x;
    if (c >= HW) return;
    const int x_idx = c / H, y_idx = c - x_idx * H;
    const float px = (float)x_idx * inv_wm1, py = (float)y_idx * inv_hm1;
    float g = 0.0f, acc = 0.0f;
#pragma unroll
    for (int k = 0; k < NK; k++) {
        const float d0 = px - mux[k], d1 = py - muy[k];
        const float t0 = fmaf(s00[k], d0, s10[k] * d1);
        const float t1 = s11[k] * d1;
        const float e  = __expf(-0.5f * fmaf(t0, t0, t1 * t1));
        g += e;
        acc = fmaf(wkk[k], e, acc);
    }
    out[(size_t)n * (size_t)HW + c] =
        __saturatef(__fdividef(acc, fmaxf(GM_EPS, g)));
}

// ---------------------------------------------------------------------------
extern "C" void kernel_launch(void* const* d_in, const int* in_sizes, int n_in,
                              void* d_out, int out_size)
{
    int pi = 0;
    for (int i = 1; i < n_in; i++)
        if (in_sizes[i] > in_sizes[pi]) pi = i;
    const float* params = (const float*)d_in[pi];

    const int N  = in_sizes[pi] / 28;
    const int HW = out_size / N;
    int H = (int)(sqrt((double)HW) + 0.5);
    while (H > 1 && (HW % H) != 0) H--;
    const int W = HW / H;

    const float inv_wm1 = 1.0f / (float)(W - 1);
    const float inv_hm1 = 1.0f / (float)(H - 1);

    if ((H % PIX) == 0) {
        const int threads = 256;
        const int px_per_block = threads * PIX;
        dim3 grid((HW + px_per_block - 1) / px_per_block, N);
        gmix_fd2<<<grid, threads>>>(params, (float*)d_out,
                                    H, HW, inv_wm1, inv_hm1);
    } else {
        const int threads = 256;
        dim3 grid((HW + threads - 1) / threads, N);
        gmix_generic<<<grid, threads>>>(params, (float*)d_out,
                                        H, HW, inv_wm1, inv_hm1);
    }
}

// round 7
// speedup vs baseline: 1.0365x; 1.0365x over previous
#include <cuda_runtime.h>
#include <math.h>

// Gaussian-mixture splat renderer, forward-differenced along grid columns.
// Scalar FD chains, 4-pixel batched epilogue (pipelined MUFU.RCP),
// 128-thread blocks x 12/SM -> single wave at 75% occupancy.
//
// c = x_idx*H + y_idx ; px = x_idx/(W-1), py = y_idx/(H-1).
// Per Gaussian k (prescaled by SC = sqrt(0.5*log2 e)):
//   t0 = s10*py + (s00*px + C0),  t1 = s11*py + A1,  e_k = exp2(-(t0^2+t1^2))
// FD along a column (fixed px, py stepping by h):
//   e <- e*r,  r <- r*rr,  rr = exp2(-2 h^2 (s10^2+s11^2))   [const per n,k]
// out = saturate( sum_k w_k e_k / max(1e-7, sum_k e_k) )

#define NK 4
#define PIX 32
#define THR 128
#define GM_EPS 1e-7f

__device__ __forceinline__ float ex2(float x) {
    float y; asm("ex2.approx.ftz.f32 %0, %1;" : "=f"(y) : "f"(x)); return y;
}
__device__ __forceinline__ float frcp(float x) {
    float y; asm("rcp.approx.ftz.f32 %0, %1;" : "=f"(y) : "f"(x)); return y;
}

// ---------------------------------------------------------------------------
// Main kernel: each thread renders PIX consecutive pixels of one column.
// Requires H % PIX == 0.
// ---------------------------------------------------------------------------
__global__ void __launch_bounds__(THR, 12) gmix_fd(
    const float* __restrict__ params,
    float* __restrict__ out,
    int H, int HW, float inv_wm1, float inv_hm1)
{
    const int n  = blockIdx.y;
    const int c0 = (blockIdx.x * THR + threadIdx.x) * PIX;
    if (c0 >= HW) return;

    const float4* p4 = reinterpret_cast<const float4*>(params + n * 28);
    const float4 MUX = __ldg(p4 + 0);
    const float4 MUY = __ldg(p4 + 1);
    const float4 WKV = __ldg(p4 + 2);
    const float4 SG0 = __ldg(p4 + 3);   // {s00, s01(ignored), s10, s11}
    const float4 SG1 = __ldg(p4 + 4);
    const float4 SG2 = __ldg(p4 + 5);
    const float4 SG3 = __ldg(p4 + 6);

    const float mux[NK] = {MUX.x, MUX.y, MUX.z, MUX.w};
    const float muy[NK] = {MUY.x, MUY.y, MUY.z, MUY.w};
    const float wk [NK] = {WKV.x, WKV.y, WKV.z, WKV.w};
    const float SC = 0.84932180f;       // sqrt(0.5 * log2 e)
    const float s00[NK] = {SG0.x * SC, SG1.x * SC, SG2.x * SC, SG3.x * SC};
    const float s10[NK] = {SG0.z * SC, SG1.z * SC, SG2.z * SC, SG3.z * SC};
    const float s11[NK] = {SG0.w * SC, SG1.w * SC, SG2.w * SC, SG3.w * SC};

    const int   x_idx = c0 / H;
    const int   y0    = c0 - x_idx * H;
    const float px    = (float)x_idx * inv_wm1;
    const float py0   = (float)y0 * inv_hm1;
    const float h     = inv_hm1;

    // Derive FD constants, seed e and r at the first pixel of this run.
    float e[NK], r[NK], rr[NK];
#pragma unroll
    for (int k = 0; k < NK; k++) {
        const float C0  = -(s00[k] * mux[k] + s10[k] * muy[k]);
        const float A1  = -s11[k] * muy[k];
        const float a   = fmaf(s10[k], s10[k], s11[k] * s11[k]);
        const float w0n = -(h * h) * a;
        const float un  = -2.0f * h * s10[k];
        const float vn  = -2.0f * h * s11[k];
        rr[k] = ex2(w0n + w0n);

        const float a0 = fmaf(s00[k], px, C0);
        const float t0 = fmaf(s10[k], py0, a0);
        const float t1 = fmaf(s11[k], py0, A1);
        e[k] = ex2(fmaf(-t0, t0, -t1 * t1));
        r[k] = ex2(fmaf(un, t0, fmaf(vn, t1, w0n)));
    }

    float4* outv = reinterpret_cast<float4*>(out + (size_t)n * (size_t)HW + c0);

#pragma unroll
    for (int grp = 0; grp < PIX / 4; grp++) {
        // Phase 1: mixture sums for 4 pixels (FD chains advance between them).
        // The eps-floor is applied here so phase 2 is a pure RCP->MUL->SAT.
        float gg[4], aa[4];
#pragma unroll
        for (int q = 0; q < 4; q++) {
            if (!(grp == 0 && q == 0)) {
                e[0] *= r[0];  e[1] *= r[1];  e[2] *= r[2];  e[3] *= r[3];
                r[0] *= rr[0]; r[1] *= rr[1]; r[2] *= rr[2]; r[3] *= rr[3];
            }
            gg[q] = fmaxf(GM_EPS, (e[0] + e[1]) + (e[2] + e[3]));
            aa[q] = fmaf(wk[0], e[0],
                    fmaf(wk[1], e[1],
                    fmaf(wk[2], e[2], wk[3] * e[3])));
        }
        // Phase 2: batched epilogue — 4 RCPs pipeline through MUFU; their
        // latency overlaps each other and the next group's chain FMULs.
        const float i0 = frcp(gg[0]);
        const float i1 = frcp(gg[1]);
        const float i2 = frcp(gg[2]);
        const float i3 = frcp(gg[3]);
        float4 res;
        res.x = __saturatef(aa[0] * i0);
        res.y = __saturatef(aa[1] * i1);
        res.z = __saturatef(aa[2] * i2);
        res.w = __saturatef(aa[3] * i3);
        outv[grp] = res;
    }
}

// ---------------------------------------------------------------------------
// Fallback: per-pixel direct evaluation (H % PIX != 0).
// ---------------------------------------------------------------------------
__global__ void __launch_bounds__(256) gmix_generic(
    const float* __restrict__ params,
    float* __restrict__ out,
    int H, int HW, float inv_wm1, float inv_hm1)
{
    const int n = blockIdx.y;
    const float* p = params + n * 28;
    float mux[NK], muy[NK], wkk[NK], s00[NK], s10[NK], s11[NK];
#pragma unroll
    for (int k = 0; k < NK; k++) {
        mux[k] = __ldg(p + k);        muy[k] = __ldg(p + 4 + k);
        wkk[k] = __ldg(p + 8 + k);
        s00[k] = __ldg(p + 12 + 4*k + 0);
        s10[k] = __ldg(p + 12 + 4*k + 2);
        s11[k] = __ldg(p + 12 + 4*k + 3);
    }
    const int c = blockIdx.x * blockDim.x + threadIdx.x;
    if (c >= HW) return;
    const int x_idx = c / H, y_idx = c - x_idx * H;
    const float px = (float)x_idx * inv_wm1, py = (float)y_idx * inv_hm1;
    float g = 0.0f, acc = 0.0f;
#pragma unroll
    for (int k = 0; k < NK; k++) {
        const float d0 = px - mux[k], d1 = py - muy[k];
        const float t0 = fmaf(s00[k], d0, s10[k] * d1);
        const float t1 = s11[k] * d1;
        const float e  = __expf(-0.5f * fmaf(t0, t0, t1 * t1));
        g += e;
        acc = fmaf(wkk[k], e, acc);
    }
    out[(size_t)n * (size_t)HW + c] =
        __saturatef(__fdividef(acc, fmaxf(GM_EPS, g)));
}

// ---------------------------------------------------------------------------
extern "C" void kernel_launch(void* const* d_in, const int* in_sizes, int n_in,
                              void* d_out, int out_size)
{
    int pi = 0;
    for (int i = 1; i < n_in; i++)
        if (in_sizes[i] > in_sizes[pi]) pi = i;
    const float* params = (const float*)d_in[pi];

    const int N  = in_sizes[pi] / 28;
    const int HW = out_size / N;
    int H = (int)(sqrt((double)HW) + 0.5);
    while (H > 1 && (HW % H) != 0) H--;
    const int W = HW / H;

    const float inv_wm1 = 1.0f / (float)(W - 1);
    const float inv_hm1 = 1.0f / (float)(H - 1);

    if ((H % PIX) == 0) {
        const int px_per_block = THR * PIX;
        dim3 grid((HW + px_per_block - 1) / px_per_block, N);
        gmix_fd<<<grid, THR>>>(params, (float*)d_out,
                               H, HW, inv_wm1, inv_hm1);
    } else {
        const int threads = 256;
        dim3 grid((HW + threads - 1) / threads, N);
        gmix_generic<<<grid, threads>>>(params, (float*)d_out,
                                        H, HW, inv_wm1, inv_hm1);
    }
}

// round 8
// speedup vs baseline: 1.3069x; 1.2609x over previous
#include <cuda_runtime.h>
#include <math.h>

// Gaussian-mixture splat renderer, forward-differenced along grid columns.
// R4 math exactly; stores staged through a per-warp SMEM tile so GMEM
// writes are fully coalesced (512B per warp-store instead of 32 scattered
// 16B partial-line writes).
//
// c = x_idx*H + y_idx ; px = x_idx/(W-1), py = y_idx/(H-1).
// Per Gaussian k (prescaled by SC = sqrt(0.5*log2 e)):
//   t0 = s10*py + (s00*px + C0),  t1 = s11*py + A1,  e_k = exp2(-(t0^2+t1^2))
// FD along a column: e <- e*r, r <- r*rr, rr = exp2(-2 h^2 (s10^2+s11^2))
// out = saturate( sum_k w_k e_k / max(1e-7, sum_k e_k) )

#define NK 4
#define PIX 32
#define THR 128          // 4 warps
#define WARPS 4
#define GM_EPS 1e-7f

__device__ __forceinline__ float ex2(float x) {
    float y; asm("ex2.approx.ftz.f32 %0, %1;" : "=f"(y) : "f"(x)); return y;
}

// ---------------------------------------------------------------------------
// Main kernel. Lane l of global-warp gw owns pixels [gw*1024 + 32l, +32).
// Requires H % 32 == 0 and HW % 4096 == 0.
//
// SMEM tile layout (per warp, float4 units, 9 per lane-row = 16B pad/row):
//   write:  idx = 9*l + g            (banks 4l+4g per 8-lane phase: disjoint)
//   read :  idx = 36*i + l + (l>>3)  (banks 4l per phase: disjoint)
// Read idx equals write idx of the producing lane for output float4 f=32i+l.
// ---------------------------------------------------------------------------
__global__ void __launch_bounds__(THR, 12) gmix_fd(
    const float* __restrict__ params,
    float* __restrict__ out,
    int H, int HW, float inv_wm1, float inv_hm1)
{
    __shared__ float4 tile[WARPS][288];   // 4 * 4608 B = 18432 B

    const int warp = threadIdx.x >> 5;
    const int lane = threadIdx.x & 31;
    const int gw   = blockIdx.x * WARPS + warp;
    const int n    = blockIdx.y;
    const int c0   = gw * (32 * PIX) + lane * PIX;
    if (c0 >= HW) return;

    const float4* p4 = reinterpret_cast<const float4*>(params + n * 28);
    const float4 MUX = __ldg(p4 + 0);
    const float4 MUY = __ldg(p4 + 1);
    const float4 WKV = __ldg(p4 + 2);
    const float4 SG0 = __ldg(p4 + 3);   // {s00, s01(ignored), s10, s11}
    const float4 SG1 = __ldg(p4 + 4);
    const float4 SG2 = __ldg(p4 + 5);
    const float4 SG3 = __ldg(p4 + 6);

    const float mux[NK] = {MUX.x, MUX.y, MUX.z, MUX.w};
    const float muy[NK] = {MUY.x, MUY.y, MUY.z, MUY.w};
    const float wk [NK] = {WKV.x, WKV.y, WKV.z, WKV.w};
    const float SC = 0.84932180f;       // sqrt(0.5 * log2 e)
    const float s00[NK] = {SG0.x * SC, SG1.x * SC, SG2.x * SC, SG3.x * SC};
    const float s10[NK] = {SG0.z * SC, SG1.z * SC, SG2.z * SC, SG3.z * SC};
    const float s11[NK] = {SG0.w * SC, SG1.w * SC, SG2.w * SC, SG3.w * SC};

    const int   x_idx = c0 / H;
    const int   y0    = c0 - x_idx * H;
    const float px    = (float)x_idx * inv_wm1;
    const float py0   = (float)y0 * inv_hm1;
    const float h     = inv_hm1;

    // Derive FD constants, seed e and r at the first pixel of this run.
    float e[NK], r[NK], rr[NK];
#pragma unroll
    for (int k = 0; k < NK; k++) {
        const float C0  = -(s00[k] * mux[k] + s10[k] * muy[k]);
        const float A1  = -s11[k] * muy[k];
        const float a   = fmaf(s10[k], s10[k], s11[k] * s11[k]);
        const float w0n = -(h * h) * a;
        const float un  = -2.0f * h * s10[k];
        const float vn  = -2.0f * h * s11[k];
        rr[k] = ex2(w0n + w0n);

        const float a0 = fmaf(s00[k], px, C0);
        const float t0 = fmaf(s10[k], py0, a0);
        const float t1 = fmaf(s11[k], py0, A1);
        e[k] = ex2(fmaf(-t0, t0, -t1 * t1));
        r[k] = ex2(fmaf(un, t0, fmaf(vn, t1, w0n)));
    }

    float4* tw = tile[warp];

#pragma unroll
    for (int grp = 0; grp < PIX / 4; grp++) {
        float4 res;
        float* rp = &res.x;
#pragma unroll
        for (int q = 0; q < 4; q++) {
            if (!(grp == 0 && q == 0)) {
                e[0] *= r[0];  e[1] *= r[1];  e[2] *= r[2];  e[3] *= r[3];
                r[0] *= rr[0]; r[1] *= rr[1]; r[2] *= rr[2]; r[3] *= rr[3];
            }
            const float g   = (e[0] + e[1]) + (e[2] + e[3]);
            const float acc = fmaf(wk[0], e[0],
                              fmaf(wk[1], e[1],
                              fmaf(wk[2], e[2], wk[3] * e[3])));
            rp[q] = __saturatef(__fdividef(acc, fmaxf(GM_EPS, g)));
        }
        tw[9 * lane + grp] = res;                  // STS.128, conflict-free
    }

    __syncwarp();

    // Coalesced drain: warp writes 8 x 512B contiguous chunks.
    float4* ob = reinterpret_cast<float4*>(out + (size_t)n * (size_t)HW
                                               + (size_t)gw * (32 * PIX));
#pragma unroll
    for (int i = 0; i < 8; i++) {
        ob[32 * i + lane] = tw[36 * i + lane + (lane >> 3)];  // LDS.128 + STG.128
    }
}

// ---------------------------------------------------------------------------
// Fallback: per-pixel direct evaluation (odd shapes).
// ---------------------------------------------------------------------------
__global__ void __launch_bounds__(256) gmix_generic(
    const float* __restrict__ params,
    float* __restrict__ out,
    int H, int HW, float inv_wm1, float inv_hm1)
{
    const int n = blockIdx.y;
    const float* p = params + n * 28;
    float mux[NK], muy[NK], wkk[NK], s00[NK], s10[NK], s11[NK];
#pragma unroll
    for (int k = 0; k < NK; k++) {
        mux[k] = __ldg(p + k);        muy[k] = __ldg(p + 4 + k);
        wkk[k] = __ldg(p + 8 + k);
        s00[k] = __ldg(p + 12 + 4*k + 0);
        s10[k] = __ldg(p + 12 + 4*k + 2);
        s11[k] = __ldg(p + 12 + 4*k + 3);
    }
    const int c = blockIdx.x * blockDim.x + threadIdx.x;
    if (c >= HW) return;
    const int x_idx = c / H, y_idx = c - x_idx * H;
    const float px = (float)x_idx * inv_wm1, py = (float)y_idx * inv_hm1;
    float g = 0.0f, acc = 0.0f;
#pragma unroll
    for (int k = 0; k < NK; k++) {
        const float d0 = px - mux[k], d1 = py - muy[k];
        const float t0 = fmaf(s00[k], d0, s10[k] * d1);
        const float t1 = s11[k] * d1;
        const float e  = __expf(-0.5f * fmaf(t0, t0, t1 * t1));
        g += e;
        acc = fmaf(wkk[k], e, acc);
    }
    out[(size_t)n * (size_t)HW + c] =
        __saturatef(__fdividef(acc, fmaxf(GM_EPS, g)));
}

// ---------------------------------------------------------------------------
extern "C" void kernel_launch(void* const* d_in, const int* in_sizes, int n_in,
                              void* d_out, int out_size)
{
    int pi = 0;
    for (int i = 1; i < n_in; i++)
        if (in_sizes[i] > in_sizes[pi]) pi = i;
    const float* params = (const float*)d_in[pi];

    const int N  = in_sizes[pi] / 28;
    const int HW = out_size / N;
    int H = (int)(sqrt((double)HW) + 0.5);
    while (H > 1 && (HW % H) != 0) H--;
    const int W = HW / H;

    const float inv_wm1 = 1.0f / (float)(W - 1);
    const float inv_hm1 = 1.0f / (float)(H - 1);

    const int px_per_block = THR * PIX;   // 4096
    if ((H % PIX) == 0 && (HW % px_per_block) == 0) {
        dim3 grid(HW / px_per_block, N);
        gmix_fd<<<grid, THR>>>(params, (float*)d_out,
                               H, HW, inv_wm1, inv_hm1);
    } else {
        const int threads = 256;
        dim3 grid((HW + threads - 1) / threads, N);
        gmix_generic<<<grid, threads>>>(params, (float*)d_out,
                                        H, HW, inv_wm1, inv_hm1);
    }
}

// round 9
// speedup vs baseline: 1.3273x; 1.0156x over previous
#include <cuda_runtime.h>
#include <math.h>

// Gaussian-mixture splat renderer, forward-differenced along grid columns.
// R8 structure (SMEM-staged coalesced stores) + FD chains packed into
// fma.rn.f32x2 (FFMA2): 8 chain FMULs/pixel -> 4 packed FMAs/pixel.
// Epilogue stays scalar on the register-pair halves (no unpack churn).
//
// c = x_idx*H + y_idx ; px = x_idx/(W-1), py = y_idx/(H-1).
// Per Gaussian k (prescaled by SC = sqrt(0.5*log2 e)):
//   t0 = s10*py + (s00*px + C0),  t1 = s11*py + A1,  e_k = exp2(-(t0^2+t1^2))
// FD along a column: e <- e*r, r <- r*rr, rr = exp2(-2 h^2 (s10^2+s11^2))
// out = saturate( sum_k w_k e_k / max(1e-7, sum_k e_k) )

#define NK 4
#define PIX 32
#define THR 128          // 4 warps
#define WARPS 4
#define GM_EPS 1e-7f

typedef unsigned long long u64t;

__device__ __forceinline__ float ex2(float x) {
    float y; asm("ex2.approx.ftz.f32 %0, %1;" : "=f"(y) : "f"(x)); return y;
}
__device__ __forceinline__ u64t pk2(float lo, float hi) {
    u64t r; asm("mov.b64 %0, {%1, %2};" : "=l"(r) : "f"(lo), "f"(hi)); return r;
}
__device__ __forceinline__ void upk2(u64t v, float& lo, float& hi) {
    asm("mov.b64 {%0, %1}, %2;" : "=f"(lo), "=f"(hi) : "l"(v));
}
__device__ __forceinline__ u64t fma2(u64t a, u64t b, u64t c) {
    u64t d; asm("fma.rn.f32x2 %0, %1, %2, %3;" : "=l"(d) : "l"(a), "l"(b), "l"(c)); return d;
}

// ---------------------------------------------------------------------------
// Main kernel. Lane l of global-warp gw owns pixels [gw*1024 + 32l, +32).
// Requires H % 32 == 0 and HW % 4096 == 0.
// SMEM tile: write tw[9*l + g] (conflict-free), read tw[36*i + l + (l>>3)].
// ---------------------------------------------------------------------------
__global__ void __launch_bounds__(THR, 12) gmix_fd(
    const float* __restrict__ params,
    float* __restrict__ out,
    int H, int HW, float inv_wm1, float inv_hm1)
{
    __shared__ float4 tile[WARPS][288];   // 18432 B

    const int warp = threadIdx.x >> 5;
    const int lane = threadIdx.x & 31;
    const int gw   = blockIdx.x * WARPS + warp;
    const int n    = blockIdx.y;
    const int c0   = gw * (32 * PIX) + lane * PIX;
    if (c0 >= HW) return;

    const float4* p4 = reinterpret_cast<const float4*>(params + n * 28);
    const float4 MUX = __ldg(p4 + 0);
    const float4 MUY = __ldg(p4 + 1);
    const float4 WKV = __ldg(p4 + 2);
    const float4 SG0 = __ldg(p4 + 3);   // {s00, s01(ignored), s10, s11}
    const float4 SG1 = __ldg(p4 + 4);
    const float4 SG2 = __ldg(p4 + 5);
    const float4 SG3 = __ldg(p4 + 6);

    const float mux[NK] = {MUX.x, MUX.y, MUX.z, MUX.w};
    const float muy[NK] = {MUY.x, MUY.y, MUY.z, MUY.w};
    const float wk [NK] = {WKV.x, WKV.y, WKV.z, WKV.w};
    const float SC = 0.84932180f;       // sqrt(0.5 * log2 e)
    const float s00[NK] = {SG0.x * SC, SG1.x * SC, SG2.x * SC, SG3.x * SC};
    const float s10[NK] = {SG0.z * SC, SG1.z * SC, SG2.z * SC, SG3.z * SC};
    const float s11[NK] = {SG0.w * SC, SG1.w * SC, SG2.w * SC, SG3.w * SC};

    const int   x_idx = c0 / H;
    const int   y0    = c0 - x_idx * H;
    const float px    = (float)x_idx * inv_wm1;
    const float py0   = (float)y0 * inv_hm1;
    const float h     = inv_hm1;

    // Derive FD constants, seed e and r at the first pixel of this run.
    float es[NK], rs[NK], rrs[NK];
#pragma unroll
    for (int k = 0; k < NK; k++) {
        const float C0  = -(s00[k] * mux[k] + s10[k] * muy[k]);
        const float A1  = -s11[k] * muy[k];
        const float a   = fmaf(s10[k], s10[k], s11[k] * s11[k]);
        const float w0n = -(h * h) * a;
        const float un  = -2.0f * h * s10[k];
        const float vn  = -2.0f * h * s11[k];
        rrs[k] = ex2(w0n + w0n);

        const float a0 = fmaf(s00[k], px, C0);
        const float t0 = fmaf(s10[k], py0, a0);
        const float t1 = fmaf(s11[k], py0, A1);
        es[k] = ex2(fmaf(-t0, t0, -t1 * t1));
        rs[k] = ex2(fmaf(un, t0, fmaf(vn, t1, w0n)));
    }

    // Packed chain state: same register footprint as the scalar version.
    u64t E01 = pk2(es[0], es[1]), E23 = pk2(es[2], es[3]);
    u64t R01 = pk2(rs[0], rs[1]), R23 = pk2(rs[2], rs[3]);
    const u64t RR01 = pk2(rrs[0], rrs[1]), RR23 = pk2(rrs[2], rrs[3]);
    const u64t Z2 = pk2(0.0f, 0.0f);

    float4* tw = tile[warp];

#pragma unroll
    for (int grp = 0; grp < PIX / 4; grp++) {
        float4 res;
        float* rp = &res.x;
#pragma unroll
        for (int q = 0; q < 4; q++) {
            if (!(grp == 0 && q == 0)) {
                // 4 packed FMAs replace 8 scalar FMULs.
                E01 = fma2(E01, R01, Z2);
                E23 = fma2(E23, R23, Z2);
                R01 = fma2(R01, RR01, Z2);
                R23 = fma2(R23, RR23, Z2);
            }
            // Scalar epilogue on the register-pair halves.
            float e0, e1, e2, e3;
            upk2(E01, e0, e1);
            upk2(E23, e2, e3);
            const float g   = (e0 + e1) + (e2 + e3);
            const float acc = fmaf(wk[0], e0,
                              fmaf(wk[1], e1,
                              fmaf(wk[2], e2, wk[3] * e3)));
            rp[q] = __saturatef(__fdividef(acc, fmaxf(GM_EPS, g)));
        }
        tw[9 * lane + grp] = res;                  // STS.128, conflict-free
    }

    __syncwarp();

    // Coalesced drain: warp writes 8 x 512B contiguous chunks.
    float4* ob = reinterpret_cast<float4*>(out + (size_t)n * (size_t)HW
                                               + (size_t)gw * (32 * PIX));
#pragma unroll
    for (int i = 0; i < 8; i++) {
        ob[32 * i + lane] = tw[36 * i + lane + (lane >> 3)];
    }
}

// ---------------------------------------------------------------------------
// Fallback: per-pixel direct evaluation (odd shapes).
// ---------------------------------------------------------------------------
__global__ void __launch_bounds__(256) gmix_generic(
    const float* __restrict__ params,
    float* __restrict__ out,
    int H, int HW, float inv_wm1, float inv_hm1)
{
    const int n = blockIdx.y;
    const float* p = params + n * 28;
    float mux[NK], muy[NK], wkk[NK], s00[NK], s10[NK], s11[NK];
#pragma unroll
    for (int k = 0; k < NK; k++) {
        mux[k] = __ldg(p + k);        muy[k] = __ldg(p + 4 + k);
        wkk[k] = __ldg(p + 8 + k);
        s00[k] = __ldg(p + 12 + 4*k + 0);
        s10[k] = __ldg(p + 12 + 4*k + 2);
        s11[k] = __ldg(p + 12 + 4*k + 3);
    }
    const int c = blockIdx.x * blockDim.x + threadIdx.x;
    if (c >= HW) return;
    const int x_idx = c / H, y_idx = c - x_idx * H;
    const float px = (float)x_idx * inv_wm1, py = (float)y_idx * inv_hm1;
    float g = 0.0f, acc = 0.0f;
#pragma unroll
    for (int k = 0; k < NK; k++) {
        const float d0 = px - mux[k], d1 = py - muy[k];
        const float t0 = fmaf(s00[k], d0, s10[k] * d1);
        const float t1 = s11[k] * d1;
        const float e  = __expf(-0.5f * fmaf(t0, t0, t1 * t1));
        g += e;
        acc = fmaf(wkk[k], e, acc);
    }
    out[(size_t)n * (size_t)HW + c] =
        __saturatef(__fdividef(acc, fmaxf(GM_EPS, g)));
}

// ---------------------------------------------------------------------------
extern "C" void kernel_launch(void* const* d_in, const int* in_sizes, int n_in,
                              void* d_out, int out_size)
{
    int pi = 0;
    for (int i = 1; i < n_in; i++)
        if (in_sizes[i] > in_sizes[pi]) pi = i;
    const float* params = (const float*)d_in[pi];

    const int N  = in_sizes[pi] / 28;
    const int HW = out_size / N;
    int H = (int)(sqrt((double)HW) + 0.5);
    while (H > 1 && (HW % H) != 0) H--;
    const int W = HW / H;

    const float inv_wm1 = 1.0f / (float)(W - 1);
    const float inv_hm1 = 1.0f / (float)(H - 1);

    const int px_per_block = THR * PIX;   // 4096
    if ((H % PIX) == 0 && (HW % px_per_block) == 0) {
        dim3 grid(HW / px_per_block, N);
        gmix_fd<<<grid, THR>>>(params, (float*)d_out,
                               H, HW, inv_wm1, inv_hm1);
    } else {
        const int threads = 256;
        dim3 grid((HW + threads - 1) / threads, N);
        gmix_generic<<<grid, threads>>>(params, (float*)d_out,
                                        H, HW, inv_wm1, inv_hm1);
    }
}

// round 10
// speedup vs baseline: 1.3307x; 1.0026x over previous
#include <cuda_runtime.h>
#include <math.h>

// Gaussian-mixture splat renderer, forward-differenced along grid columns.
// R8/R9 structure (SMEM-staged coalesced stores, packed FD chains) plus a
// packed epilogue: mixture sums computed directly on the packed E state.
//
// c = x_idx*H + y_idx ; px = x_idx/(W-1), py = y_idx/(H-1).
// Per Gaussian k (prescaled by SC = sqrt(0.5*log2 e)):
//   t0 = s10*py + (s00*px + C0),  t1 = s11*py + A1,  e_k = exp2(-(t0^2+t1^2))
// FD along a column: e <- e*r, r <- r*rr, rr = exp2(-2 h^2 (s10^2+s11^2))
// out = saturate( sum_k w_k e_k / max(1e-7, sum_k e_k) )

#define NK 4
#define PIX 32
#define THR 128          // 4 warps
#define WARPS 4
#define GM_EPS 1e-7f

typedef unsigned long long u64t;

__device__ __forceinline__ float ex2(float x) {
    float y; asm("ex2.approx.ftz.f32 %0, %1;" : "=f"(y) : "f"(x)); return y;
}
__device__ __forceinline__ u64t pk2(float lo, float hi) {
    u64t r; asm("mov.b64 %0, {%1, %2};" : "=l"(r) : "f"(lo), "f"(hi)); return r;
}
__device__ __forceinline__ void upk2(u64t v, float& lo, float& hi) {
    asm("mov.b64 {%0, %1}, %2;" : "=f"(lo), "=f"(hi) : "l"(v));
}
__device__ __forceinline__ u64t mul2(u64t a, u64t b) {
    u64t d; asm("mul.rn.f32x2 %0, %1, %2;" : "=l"(d) : "l"(a), "l"(b)); return d;
}
__device__ __forceinline__ u64t add2(u64t a, u64t b) {
    u64t d; asm("add.rn.f32x2 %0, %1, %2;" : "=l"(d) : "l"(a), "l"(b)); return d;
}
__device__ __forceinline__ u64t fma2(u64t a, u64t b, u64t c) {
    u64t d; asm("fma.rn.f32x2 %0, %1, %2, %3;" : "=l"(d) : "l"(a), "l"(b), "l"(c)); return d;
}

// ---------------------------------------------------------------------------
// Main kernel. Lane l of global-warp gw owns pixels [gw*1024 + 32l, +32).
// Requires H % 32 == 0 and HW % 4096 == 0.
// SMEM tile: write tw[9*l + g] (conflict-free), read tw[36*i + l + (l>>3)].
// ---------------------------------------------------------------------------
__global__ void __launch_bounds__(THR, 12) gmix_fd(
    const float* __restrict__ params,
    float* __restrict__ out,
    int H, int HW, float inv_wm1, float inv_hm1)
{
    __shared__ float4 tile[WARPS][288];   // 18432 B

    const int warp = threadIdx.x >> 5;
    const int lane = threadIdx.x & 31;
    const int gw   = blockIdx.x * WARPS + warp;
    const int n    = blockIdx.y;
    const int c0   = gw * (32 * PIX) + lane * PIX;
    if (c0 >= HW) return;

    const float4* p4 = reinterpret_cast<const float4*>(params + n * 28);
    const float4 MUX = __ldg(p4 + 0);
    const float4 MUY = __ldg(p4 + 1);
    const float4 WKV = __ldg(p4 + 2);
    const float4 SG0 = __ldg(p4 + 3);   // {s00, s01(ignored), s10, s11}
    const float4 SG1 = __ldg(p4 + 4);
    const float4 SG2 = __ldg(p4 + 5);
    const float4 SG3 = __ldg(p4 + 6);

    const float mux[NK] = {MUX.x, MUX.y, MUX.z, MUX.w};
    const float muy[NK] = {MUY.x, MUY.y, MUY.z, MUY.w};
    const float SC = 0.84932180f;       // sqrt(0.5 * log2 e)
    const float s00[NK] = {SG0.x * SC, SG1.x * SC, SG2.x * SC, SG3.x * SC};
    const float s10[NK] = {SG0.z * SC, SG1.z * SC, SG2.z * SC, SG3.z * SC};
    const float s11[NK] = {SG0.w * SC, SG1.w * SC, SG2.w * SC, SG3.w * SC};

    const int   x_idx = c0 / H;
    const int   y0    = c0 - x_idx * H;
    const float px    = (float)x_idx * inv_wm1;
    const float py0   = (float)y0 * inv_hm1;
    const float h     = inv_hm1;

    // Derive FD constants, seed e and r at the first pixel of this run.
    float es[NK], rs[NK], rrs[NK];
#pragma unroll
    for (int k = 0; k < NK; k++) {
        const float C0  = -(s00[k] * mux[k] + s10[k] * muy[k]);
        const float A1  = -s11[k] * muy[k];
        const float a   = fmaf(s10[k], s10[k], s11[k] * s11[k]);
        const float w0n = -(h * h) * a;
        const float un  = -2.0f * h * s10[k];
        const float vn  = -2.0f * h * s11[k];
        rrs[k] = ex2(w0n + w0n);

        const float a0 = fmaf(s00[k], px, C0);
        const float t0 = fmaf(s10[k], py0, a0);
        const float t1 = fmaf(s11[k], py0, A1);
        es[k] = ex2(fmaf(-t0, t0, -t1 * t1));
        rs[k] = ex2(fmaf(un, t0, fmaf(vn, t1, w0n)));
    }

    // Packed chain state over k-pairs.
    u64t E01 = pk2(es[0], es[1]), E23 = pk2(es[2], es[3]);
    u64t R01 = pk2(rs[0], rs[1]), R23 = pk2(rs[2], rs[3]);
    const u64t RR01 = pk2(rrs[0], rrs[1]), RR23 = pk2(rrs[2], rrs[3]);
    const u64t W01  = pk2(WKV.x, WKV.y),   W23  = pk2(WKV.z, WKV.w);

    float4* tw = tile[warp];

#pragma unroll
    for (int grp = 0; grp < PIX / 4; grp++) {
        float4 res;
        float* rp = &res.x;
#pragma unroll
        for (int q = 0; q < 4; q++) {
            if (!(grp == 0 && q == 0)) {
                E01 = mul2(E01, R01);
                E23 = mul2(E23, R23);
                R01 = mul2(R01, RR01);
                R23 = mul2(R23, RR23);
            }
            // Packed epilogue: sums computed on packed state, one unpack pair.
            const u64t G2 = add2(E01, E23);
            const u64t A2 = fma2(W01, E01, mul2(W23, E23));
            float g0, g1, a0, a1;
            upk2(G2, g0, g1);
            upk2(A2, a0, a1);
            const float g   = g0 + g1;
            const float acc = a0 + a1;
            rp[q] = __saturatef(__fdividef(acc, fmaxf(GM_EPS, g)));
        }
        tw[9 * lane + grp] = res;                  // STS.128, conflict-free
    }

    __syncwarp();

    // Coalesced drain: warp writes 8 x 512B contiguous chunks.
    float4* ob = reinterpret_cast<float4*>(out + (size_t)n * (size_t)HW
                                               + (size_t)gw * (32 * PIX));
#pragma unroll
    for (int i = 0; i < 8; i++) {
        ob[32 * i + lane] = tw[36 * i + lane + (lane >> 3)];
    }
}

// ---------------------------------------------------------------------------
// Fallback: per-pixel direct evaluation (odd shapes).
// ---------------------------------------------------------------------------
__global__ void __launch_bounds__(256) gmix_generic(
    const float* __restrict__ params,
    float* __restrict__ out,
    int H, int HW, float inv_wm1, float inv_hm1)
{
    const int n = blockIdx.y;
    const float* p = params + n * 28;
    float mux[NK], muy[NK], wkk[NK], s00[NK], s10[NK], s11[NK];
#pragma unroll
    for (int k = 0; k < NK; k++) {
        mux[k] = __ldg(p + k);        muy[k] = __ldg(p + 4 + k);
        wkk[k] = __ldg(p + 8 + k);
        s00[k] = __ldg(p + 12 + 4*k + 0);
        s10[k] = __ldg(p + 12 + 4*k + 2);
        s11[k] = __ldg(p + 12 + 4*k + 3);
    }
    const int c = blockIdx.x * blockDim.x + threadIdx.x;
    if (c >= HW) return;
    const int x_idx = c / H, y_idx = c - x_idx * H;
    const float px = (float)x_idx * inv_wm1, py = (float)y_idx * inv_hm1;
    float g = 0.0f, acc = 0.0f;
#pragma unroll
    for (int k = 0; k < NK; k++) {
        const float d0 = px - mux[k], d1 = py - muy[k];
        const float t0 = fmaf(s00[k], d0, s10[k] * d1);
        const float t1 = s11[k] * d1;
        const float e  = __expf(-0.5f * fmaf(t0, t0, t1 * t1));
        g += e;
        acc = fmaf(wkk[k], e, acc);
    }
    out[(size_t)n * (size_t)HW + c] =
        __saturatef(__fdividef(acc, fmaxf(GM_EPS, g)));
}

// ---------------------------------------------------------------------------
extern "C" void kernel_launch(void* const* d_in, const int* in_sizes, int n_in,
                              void* d_out, int out_size)
{
    int pi = 0;
    for (int i = 1; i < n_in; i++)
        if (in_sizes[i] > in_sizes[pi]) pi = i;
    const float* params = (const float*)d_in[pi];

    const int N  = in_sizes[pi] / 28;
    const int HW = out_size / N;
    int H = (int)(sqrt((double)HW) + 0.5);
    while (H > 1 && (HW % H) != 0) H--;
    const int W = HW / H;

    const float inv_wm1 = 1.0f / (float)(W - 1);
    const float inv_hm1 = 1.0f / (float)(H - 1);

    const int px_per_block = THR * PIX;   // 4096
    if ((H % PIX) == 0 && (HW % px_per_block) == 0) {
        dim3 grid(HW / px_per_block, N);
        gmix_fd<<<grid, THR>>>(params, (float*)d_out,
                               H, HW, inv_wm1, inv_hm1);
    } else {
        const int threads = 256;
        dim3 grid((HW + threads - 1) / threads, N);
        gmix_generic<<<grid, threads>>>(params, (float*)d_out,
                                        H, HW, inv_wm1, inv_hm1);
    }
}